// round 5
// baseline (speedup 1.0000x reference)
#include <cuda_runtime.h>

// Problem constants (B=128, T=512, X=64, H=256)
#define B_      128
#define T_      512
#define X_      64
#define H_      256
#define KK      320            // H + X combined contraction
#define CLUSTER 8
#define NGROUP  16
#define GRID_   (NGROUP * CLUSTER)   // 128 CTAs
#define NTHR    320                  // 10 warps

// ---- smem layout (float offsets) ----
#define OFF_WRZ  0        // float2[320][32]  (20480 floats)
#define OFF_WN   20480    // float [320][32]  (10240)
#define OFF_WO   30720    // float [256][8]   (2048)   Wo[kk][xl]
#define OFF_HIN  32768    // float [2][256][8] (4096)  h inbox, parity-buffered
#define OFF_XIN  36864    // float [2][64][8]  (1024)  x inbox
#define OFF_HID  37888    // float [320][8]    (2560)  combined GEMM input
#define OFF_SP   40448    // float [256][8]    (2048)  skip_p staging
#define OFF_RED  42496    // float [10][8][32][3] (7680)
#define OFF_REDP 50176    // u64  [256]        (512 floats)
#define OFF_HLOC 50688    // float[32][8]      (256)
#define OFF_OLOC 50944    // float[8][8]       (64)
#define OFF_M0   51008    // float[512]
#define OFF_M1   51520    // float[512]
#define SMEM_FLOATS 52032
#define SMEM_BYTES  (SMEM_FLOATS * 4)   // 208128 B

// GRU hidden history buf[t][b][k] for skip connections (write-once slots)
__device__ float g_buf[(size_t)T_ * B_ * H_];

// ---- packed f32x2 helpers ----
__device__ __forceinline__ unsigned long long pk2(float a, float b) {
    unsigned long long r;
    asm("mov.b64 %0, {%1, %2};" : "=l"(r) : "f"(a), "f"(b));
    return r;
}
__device__ __forceinline__ void fma2(unsigned long long& d,
                                     unsigned long long a, unsigned long long b) {
    asm("fma.rn.f32x2 %0, %1, %2, %0;" : "+l"(d) : "l"(a), "l"(b));
}
__device__ __forceinline__ unsigned long long add2(unsigned long long a,
                                                   unsigned long long b) {
    unsigned long long d;
    asm("add.rn.f32x2 %0, %1, %2;" : "=l"(d) : "l"(a), "l"(b));
    return d;
}
__device__ __forceinline__ float2 up2(unsigned long long v) {
    float2 r;
    asm("mov.b64 {%0, %1}, %2;" : "=f"(r.x), "=f"(r.y) : "l"(v));
    return r;
}

// ---- cluster / DSMEM helpers ----
__device__ __forceinline__ unsigned mapa_rank(unsigned laddr, unsigned rank) {
    unsigned r;
    asm("mapa.shared::cluster.u32 %0, %1, %2;" : "=r"(r) : "r"(laddr), "r"(rank));
    return r;
}
__device__ __forceinline__ void st_cl_v4(unsigned addr, uint4 v) {
    asm volatile("st.shared::cluster.v4.b32 [%0], {%1, %2, %3, %4};"
                 :: "r"(addr), "r"(v.x), "r"(v.y), "r"(v.z), "r"(v.w) : "memory");
}
__device__ __forceinline__ void cl_arrive() {
    asm volatile("barrier.cluster.arrive.aligned;" ::: "memory");
}
__device__ __forceinline__ void cl_wait() {
    asm volatile("barrier.cluster.wait.aligned;" ::: "memory");
}

__device__ __forceinline__ float sig_fast(float x) {
    return 1.0f / (1.0f + __expf(-x));
}
__device__ __forceinline__ float tanh_fast(float x) {
    x = fminf(15.0f, fmaxf(-15.0f, x));
    float e = __expf(-2.0f * x);
    return (1.0f - e) / (1.0f + e);
}

__device__ __forceinline__ void tables(int t, int skip, int& gidx, bool& gz,
                                       int& pidx, bool& pz, bool& late) {
    int pg = (t < skip) ? 2 * t : (t - skip);
    gz = pg < skip; gidx = pg - skip; if (gidx < 0) gidx = 0;
    int pp = (t < skip) ? 2 * t + 1 : (t - skip);
    pz = pp < skip; pidx = pp - skip; if (pidx < 0) pidx = 0;
    late = (!pz) && (pidx >= t);
}

extern __shared__ float smem[];

__global__ void __launch_bounds__(NTHR, 1) __cluster_dims__(CLUSTER, 1, 1)
decoder_kernel(
    const float* __restrict__ h_enc,
    const float* __restrict__ W_ih,
    const float* __restrict__ W_hh,
    const float* __restrict__ b_ih,
    const float* __restrict__ b_hh,
    const float* __restrict__ W_out,
    const float* __restrict__ b_out,
    const int*   __restrict__ mask0,
    const int*   __restrict__ mask1,
    const int*   __restrict__ skipp,
    float*       __restrict__ out)
{
    const int tid  = threadIdx.x;
    const int bid  = blockIdx.x;
    const int rank = bid & 7;           // cluster rank
    const int grp  = bid >> 3;
    const int b0   = grp * 8;
    const int k0   = rank * 32;         // owned h-feature base
    const int skip = skipp ? skipp[0] : 4;

    float2* Wrz  = (float2*)(smem + OFF_WRZ);
    float*  Wn   = smem + OFF_WN;
    float*  Wo   = smem + OFF_WO;
    float*  hin  = smem + OFF_HIN;
    float*  xin  = smem + OFF_XIN;
    float*  hid  = smem + OFF_HID;
    float*  sP   = smem + OFF_SP;
    float*  red  = smem + OFF_RED;
    unsigned long long* redp = (unsigned long long*)(smem + OFF_REDP);
    float*  hloc = smem + OFF_HLOC;
    float*  oloc = smem + OFF_OLOC;
    float*  m0s  = smem + OFF_M0;
    float*  m1s  = smem + OFF_M1;
    const unsigned smem_u32 = (unsigned)__cvta_generic_to_shared(smem);

    // ================= one-time staging =================
    // gate weights for features [k0, k0+32): (r,z) pairs + n, contraction-major
    for (int i = tid; i < KK * 32; i += NTHR) {
        int kk = i >> 5, kl = i & 31;
        int k  = k0 + kl;
        float r, z, n;
        if (kk < H_) {
            r = W_hh[(size_t)k * H_ + kk];
            z = W_hh[(size_t)(k + H_) * H_ + kk];
            n = W_hh[(size_t)(k + 2 * H_) * H_ + kk];
        } else {
            int xx = kk - H_;
            r = W_ih[k * X_ + xx];
            z = W_ih[(k + H_) * X_ + xx];
            n = W_ih[(k + 2 * H_) * X_ + xx];
        }
        Wrz[i] = make_float2(r, z);
        Wn[i]  = n;
    }
    // projection weights for x-cols [8*rank, 8*rank+8)
    for (int i = tid; i < H_ * 8; i += NTHR) {
        int kk = i >> 3, xl = i & 7;
        Wo[i] = W_out[(size_t)(rank * 8 + xl) * H_ + kk];
    }
    // masks
    for (int i = tid; i < T_; i += NTHR) {
        m0s[i] = (float)mask0[i];
        m1s[i] = (float)mask1[i];
    }
    // inbox parity 0: h(-1) = h_enc, x(-1) = 0 (GO token)
    for (int i = tid; i < H_ * 8; i += NTHR) {
        int kk = i >> 3, bl = i & 7;
        hin[kk * 8 + bl] = h_enc[(size_t)(b0 + bl) * H_ + kk];
    }
    for (int i = tid; i < X_ * 8; i += NTHR) xin[i] = 0.0f;

    // per-thread constants
    float br = 0.f, bz = 0.f, bnh = 0.f, bni = 0.f;   // finalize (tid < 256)
    if (tid < 256) {
        int k = k0 + (tid & 31);
        br  = b_ih[k] + b_hh[k];
        bz  = b_ih[k + H_] + b_hh[k + H_];
        bnh = b_hh[k + 2 * H_];
        bni = b_ih[k + 2 * H_];
    }
    float bo = 0.f;                                   // reduce (tid in [256,288))
    if (tid >= 256 && tid < 288) {
        int xl = (tid - 256) & 7;
        bo = b_out[rank * 8 + xl];
    }
    const int kl = tid & 31;
    const int q  = tid >> 5;                          // 0..9 contraction segment
    const float2* wrzp = Wrz + q * 32 * 32 + kl;
    const float*  wnp  = Wn  + q * 32 * 32 + kl;

    __syncthreads();
    cl_arrive(); cl_wait();     // cluster-wide: staging done everywhere

    // prefetch state (skip operands for step t, held across the barrier)
    float g[8], sp[8];
    #pragma unroll
    for (int j = 0; j < 8; ++j) { g[j] = 0.f; sp[j] = 0.f; }
    bool have = true;           // t=0: both zero, no loads needed

    for (int t = 0; t < T_; ++t) {
        int gidx, pidx; bool gz, pz, late;
        tables(t, skip, gidx, gz, pidx, pz, late);
        const bool use_sp = (!pz) && (!late);
        const int p  = t & 1;
        const int pn = p ^ 1;

        if (!have && tid < 256) {     // deferred (rare) skip-operand loads
            int kk = tid;
            #pragma unroll
            for (int j = 0; j < 8; ++j) {
                g[j]  = gz ? 0.f
                           : __ldcg(g_buf + ((size_t)gidx * B_ + b0 + j) * H_ + kk);
                sp[j] = use_sp
                           ? __ldcg(g_buf + ((size_t)pidx * B_ + b0 + j) * H_ + kk)
                           : 0.f;
            }
        }

        // ---- B: combine GEMM input + stage skip_p ----
        {
            float m0 = m0s[t], m1 = m1s[t];
            if (tid < 256) {
                int kk = tid;
                const float* hr = hin + p * 2048 + kk * 8;
                float4 a = *(const float4*)hr;
                float4 b = *(const float4*)(hr + 4);
                float4 o0 = make_float4(a.x * m0 + g[0] * m1, a.y * m0 + g[1] * m1,
                                        a.z * m0 + g[2] * m1, a.w * m0 + g[3] * m1);
                float4 o1 = make_float4(b.x * m0 + g[4] * m1, b.y * m0 + g[5] * m1,
                                        b.z * m0 + g[6] * m1, b.w * m0 + g[7] * m1);
                *(float4*)(hid + kk * 8)     = o0;
                *(float4*)(hid + kk * 8 + 4) = o1;
                *(float4*)(sP + kk * 8)     = make_float4(sp[0], sp[1], sp[2], sp[3]);
                *(float4*)(sP + kk * 8 + 4) = make_float4(sp[4], sp[5], sp[6], sp[7]);
            } else {
                int xx = tid - 256;
                const float* xr = xin + p * 512 + xx * 8;
                *(float4*)(hid + (256 + xx) * 8)     = *(const float4*)xr;
                *(float4*)(hid + (256 + xx) * 8 + 4) = *(const float4*)(xr + 4);
            }
        }
        __syncthreads();

        // ---- D: gates GEMM (all 10 warps), packed f32x2 ----
        {
            const unsigned hb = smem_u32 + OFF_HID * 4 + q * 32 * 32;
            unsigned long long ar[4], az[4], an[4];
            #pragma unroll
            for (int pp2 = 0; pp2 < 4; ++pp2) { ar[pp2] = 0; az[pp2] = 0; an[pp2] = 0; }
            #pragma unroll
            for (int i = 0; i < 32; ++i) {
                float2 wrzv = wrzp[i * 32];
                float  wnv  = wnp[i * 32];
                unsigned long long wr2 = pk2(wrzv.x, wrzv.x);
                unsigned long long wz2 = pk2(wrzv.y, wrzv.y);
                unsigned long long wn2 = pk2(wnv, wnv);
                unsigned long long h01, h23, h45, h67;
                asm("ld.shared.v2.u64 {%0, %1}, [%2];"
                    : "=l"(h01), "=l"(h23) : "r"(hb + i * 32));
                asm("ld.shared.v2.u64 {%0, %1}, [%2];"
                    : "=l"(h45), "=l"(h67) : "r"(hb + i * 32 + 16));
                fma2(ar[0], wr2, h01); fma2(ar[1], wr2, h23);
                fma2(ar[2], wr2, h45); fma2(ar[3], wr2, h67);
                fma2(az[0], wz2, h01); fma2(az[1], wz2, h23);
                fma2(az[2], wz2, h45); fma2(az[3], wz2, h67);
                fma2(an[0], wn2, h01); fma2(an[1], wn2, h23);
                fma2(an[2], wn2, h45); fma2(an[3], wn2, h67);
            }
            #pragma unroll
            for (int pp2 = 0; pp2 < 4; ++pp2) {
                float2 r2 = up2(ar[pp2]), z2 = up2(az[pp2]), n2 = up2(an[pp2]);
                float* pa = red + (((q * 8 + 2 * pp2) * 32) + kl) * 3;
                float* pb = red + (((q * 8 + 2 * pp2 + 1) * 32) + kl) * 3;
                pa[0] = r2.x; pa[1] = z2.x; pa[2] = n2.x;
                pb[0] = r2.y; pb[1] = z2.y; pb[2] = n2.y;
            }
        }

        // ---- E: projection partials (no sync needed: reads sP/hin, stable since C) ----
        if (!late && tid < 256) {
            int xl = tid & 7, blp = (tid >> 3) & 3, qq = tid >> 5;
            unsigned long long acc = 0;
            #pragma unroll 8
            for (int i = 0; i < 32; ++i) {
                int kk = qq * 32 + i;
                unsigned long long h2 = *(const unsigned long long*)(hin + p * 2048 + kk * 8 + 2 * blp);
                unsigned long long s2 = *(const unsigned long long*)(sP + kk * 8 + 2 * blp);
                s2 = add2(s2, h2);
                unsigned long long w2 = pk2(Wo[kk * 8 + xl], Wo[kk * 8 + xl]);
                fma2(acc, w2, s2);
            }
            redp[tid] = acc;
        }
        __syncthreads();

        // ---- G: finalize h(t) + projection reduce ----
        if (tid < 256) {
            int bl = tid >> 5, klf = tid & 31;
            float sr = 0.f, sz = 0.f, snh = 0.f, sni = 0.f;
            #pragma unroll
            for (int qq = 0; qq < 10; ++qq) {
                const float* pr = red + (((qq * 8 + bl) * 32) + klf) * 3;
                sr += pr[0]; sz += pr[1];
                if (qq < 8) snh += pr[2]; else sni += pr[2];
            }
            float r  = sig_fast(sr + br);
            float z  = sig_fast(sz + bz);
            float n  = tanh_fast(sni + bni + r * (snh + bnh));
            float hv = hid[(k0 + klf) * 8 + bl];
            float hn = (1.0f - z) * n + z * hv;
            hloc[klf * 8 + bl] = hn;
            __stcg(g_buf + ((size_t)t * B_ + (b0 + bl)) * H_ + (k0 + klf), hn);
        } else if (!late && tid < 288) {
            int i = tid - 256, xl = i & 7, blp = (i >> 3) & 3;
            unsigned long long a = 0;
            #pragma unroll
            for (int qq = 0; qq < 8; ++qq) a = add2(a, redp[qq * 32 + i]);
            float2 f = up2(a);
            f.x += bo; f.y += bo;
            int xg = rank * 8 + xl;
            __stcg(out + ((size_t)(b0 + 2 * blp) * T_ + t) * X_ + xg, f.x);
            __stcg(out + ((size_t)(b0 + 2 * blp + 1) * T_ + t) * X_ + xg, f.y);
            oloc[xl * 8 + 2 * blp]     = f.x;
            oloc[xl * 8 + 2 * blp + 1] = f.y;
        }
        __syncthreads();

        // ---- I: DSMEM broadcast into all peers' inboxes (parity pn) ----
        if (tid < 256) {
            #pragma unroll
            for (int s = 0; s < 2; ++s) {
                int id   = s * 256 + tid;
                int peer = ((id >> 6) + rank) & 7;
                int slot = id & 63;
                int klf  = slot >> 1, half = slot & 1;
                uint4 v = *(const uint4*)(hloc + klf * 8 + half * 4);
                unsigned la = smem_u32 + (OFF_HIN + pn * 2048 + (k0 + klf) * 8 + half * 4) * 4;
                st_cl_v4(mapa_rank(la, (unsigned)peer), v);
            }
        } else if (!late) {
            #pragma unroll
            for (int s = 0; s < 2; ++s) {
                int id   = s * 64 + (tid - 256);
                int peer = ((id >> 4) + rank) & 7;
                int slot = id & 15;
                int xl   = slot >> 1, half = slot & 1;
                uint4 v = *(const uint4*)(oloc + xl * 8 + half * 4);
                unsigned la = smem_u32 + (OFF_XIN + pn * 512 + (rank * 8 + xl) * 8 + half * 4) * 4;
                st_cl_v4(mapa_rank(la, (unsigned)peer), v);
            }
        }
        cl_arrive();

        // ---- late sub-phase (t == skip-1): projection needs h(t) ----
        if (late) {
            cl_wait();                          // h(t) now in hin[pn] everywhere
            if (tid < 256) {
                int xl = tid & 7, blp = (tid >> 3) & 3, qq = tid >> 5;
                unsigned long long acc = 0;
                #pragma unroll 8
                for (int i = 0; i < 32; ++i) {
                    int kk = qq * 32 + i;
                    unsigned long long h2 = *(const unsigned long long*)(hin + p  * 2048 + kk * 8 + 2 * blp);
                    unsigned long long n2 = *(const unsigned long long*)(hin + pn * 2048 + kk * 8 + 2 * blp);
                    unsigned long long s2 = add2(h2, n2);
                    unsigned long long w2 = pk2(Wo[kk * 8 + xl], Wo[kk * 8 + xl]);
                    fma2(acc, w2, s2);
                }
                redp[tid] = acc;
            }
            __syncthreads();
            if (tid >= 256 && tid < 288) {
                int i = tid - 256, xl = i & 7, blp = (i >> 3) & 3;
                unsigned long long a = 0;
                #pragma unroll
                for (int qq = 0; qq < 8; ++qq) a = add2(a, redp[qq * 32 + i]);
                float2 f = up2(a);
                f.x += bo; f.y += bo;
                int xg = rank * 8 + xl;
                __stcg(out + ((size_t)(b0 + 2 * blp) * T_ + t) * X_ + xg, f.x);
                __stcg(out + ((size_t)(b0 + 2 * blp + 1) * T_ + t) * X_ + xg, f.y);
                oloc[xl * 8 + 2 * blp]     = f.x;
                oloc[xl * 8 + 2 * blp + 1] = f.y;
            }
            __syncthreads();
            if (tid >= 256) {
                #pragma unroll
                for (int s = 0; s < 2; ++s) {
                    int id   = s * 64 + (tid - 256);
                    int peer = ((id >> 4) + rank) & 7;
                    int slot = id & 15;
                    int xl   = slot >> 1, half = slot & 1;
                    uint4 v = *(const uint4*)(oloc + xl * 8 + half * 4);
                    unsigned la = smem_u32 + (OFF_XIN + pn * 512 + (rank * 8 + xl) * 8 + half * 4) * 4;
                    st_cl_v4(mapa_rank(la, (unsigned)peer), v);
                }
            }
            cl_arrive();
        }

        // ---- prefetch skip operands for t+1 (overlaps barrier wait) ----
        have = false;
        if (t + 1 < T_) {
            int ngidx, npidx; bool ngz, npz, nlate;
            tables(t + 1, skip, ngidx, ngz, npidx, npz, nlate);
            bool nuse = (!npz) && (!nlate);
            bool safe = (ngz || ngidx < t) && (!nuse || npidx < t);
            if (safe) {
                if (tid < 256) {
                    int kk = tid;
                    #pragma unroll
                    for (int j = 0; j < 8; ++j) {
                        g[j]  = ngz ? 0.f
                                    : __ldcg(g_buf + ((size_t)ngidx * B_ + b0 + j) * H_ + kk);
                        sp[j] = nuse
                                    ? __ldcg(g_buf + ((size_t)npidx * B_ + b0 + j) * H_ + kk)
                                    : 0.f;
                    }
                }
                have = true;
            }
        }
        cl_wait();
    }
}

extern "C" void kernel_launch(void* const* d_in, const int* in_sizes, int n_in,
                              void* d_out, int out_size) {
    // metadata order: input, h_enc, W_ih, W_hh, b_ih, b_hh, W_out, b_out, mask0, mask1, skip_size
    const float* h_enc = (const float*)d_in[1];
    const float* W_ih  = (const float*)d_in[2];
    const float* W_hh  = (const float*)d_in[3];
    const float* b_ih  = (const float*)d_in[4];
    const float* b_hh  = (const float*)d_in[5];
    const float* W_out = (const float*)d_in[6];
    const float* b_out = (const float*)d_in[7];
    const int*   mask0 = (const int*)d_in[8];
    const int*   mask1 = (const int*)d_in[9];
    const int*   skipp = (n_in > 10) ? (const int*)d_in[10] : (const int*)0;

    cudaFuncSetAttribute(decoder_kernel,
                         cudaFuncAttributeMaxDynamicSharedMemorySize, SMEM_BYTES);
    decoder_kernel<<<GRID_, NTHR, SMEM_BYTES>>>(
        h_enc, W_ih, W_hh, b_ih, b_hh, W_out, b_out, mask0, mask1, skipp,
        (float*)d_out);
}

// round 6
// speedup vs baseline: 1.8433x; 1.8433x over previous
#include <cuda_runtime.h>

// Problem constants (B=128, T=512, X=64, H=256)
#define B_     128
#define T_     512
#define X_     64
#define H_     256
#define KK     320            // H + X combined contraction
#define NGROUP 16
#define GSIZE  8              // CTAs per group (projection folded in)
#define GRID_  (NGROUP * GSIZE)   // 128
#define NTHR   256            // 8 warps, balanced 2/SMSP

// ---- smem layout (float offsets) ----
#define OFF_WRZ  0        // float2[320][32]  (20480 floats)
#define OFF_WN   20480    // float [320][32]  (10240)
#define OFF_WO   30720    // float [256][8]   (2048)   W_out slice [kk][xl]
#define OFF_HID  32768    // float [320][8]   (2560)   gated GEMM input, kk-major
#define OFF_SP   35328    // float [256][8]   (2048)   h_prev + skip_p (projection input)
#define OFF_RED  37376    // float [256][34]  (8704)   gate partials, padded stride
#define OFF_REDP 46080    // u64   [256]      (512 floats) projection partials
#define OFF_M0   46592    // float[512]
#define OFF_M1   47104    // float[512]
#define SMEM_FLOATS 47616
#define SMEM_BYTES  (SMEM_FLOATS * 4)   // 190464 B

// GRU hidden history buf[t][b][k] (write-once slots per launch)
__device__ float    g_buf[(size_t)T_ * B_ * H_];
__device__ unsigned g_bars[NGROUP * 32];   // one counter per 128B line

__global__ void init_kernel() {
    if (threadIdx.x < NGROUP * 32) g_bars[threadIdx.x] = 0u;
}

// ---- packed f32x2 helpers ----
__device__ __forceinline__ unsigned long long pk2(float a, float b) {
    unsigned long long r;
    asm("mov.b64 %0, {%1, %2};" : "=l"(r) : "f"(a), "f"(b));
    return r;
}
__device__ __forceinline__ void fma2(unsigned long long& d,
                                     unsigned long long a, unsigned long long b) {
    asm("fma.rn.f32x2 %0, %1, %2, %0;" : "+l"(d) : "l"(a), "l"(b));
}
__device__ __forceinline__ unsigned long long add2(unsigned long long a,
                                                   unsigned long long b) {
    unsigned long long d;
    asm("add.rn.f32x2 %0, %1, %2;" : "=l"(d) : "l"(a), "l"(b));
    return d;
}
__device__ __forceinline__ float2 up2(unsigned long long v) {
    float2 r;
    asm("mov.b64 {%0, %1}, %2;" : "=f"(r.x), "=f"(r.y) : "l"(v));
    return r;
}

// ---- barrier primitives: release-reduction arrive + acquire-load poll ----
__device__ __forceinline__ void bar_arrive(unsigned* p) {
    asm volatile("red.release.gpu.add.u32 [%0], %1;" :: "l"(p), "r"(1u) : "memory");
}
__device__ __forceinline__ unsigned bar_ld(unsigned* p) {
    unsigned v;
    asm volatile("ld.acquire.gpu.b32 %0, [%1];" : "=r"(v) : "l"(p) : "memory");
    return v;
}

__device__ __forceinline__ float sig_fast(float x) {
    return 1.0f / (1.0f + __expf(-x));
}
__device__ __forceinline__ float tanh_fast(float x) {
    x = fminf(15.0f, fmaxf(-15.0f, x));
    float e = __expf(-2.0f * x);
    return (1.0f - e) / (1.0f + e);
}

__device__ __forceinline__ void tables(int t, int skip, int& gidx, bool& gz,
                                       int& pidx, bool& pz, bool& late) {
    int pg = (t < skip) ? 2 * t : (t - skip);
    gz = pg < skip; gidx = pg - skip; if (gidx < 0) gidx = 0;
    int pp = (t < skip) ? 2 * t + 1 : (t - skip);
    pz = pp < skip; pidx = pp - skip; if (pidx < 0) pidx = 0;
    late = (!pz) && (pidx >= t);
}

extern __shared__ float smem[];

__global__ void __launch_bounds__(NTHR, 1) decoder_kernel(
    const float* __restrict__ h_enc,
    const float* __restrict__ W_ih,
    const float* __restrict__ W_hh,
    const float* __restrict__ b_ih,
    const float* __restrict__ b_hh,
    const float* __restrict__ W_out,
    const float* __restrict__ b_out,
    const int*   __restrict__ mask0,
    const int*   __restrict__ mask1,
    const int*   __restrict__ skipp,
    float*       __restrict__ out)
{
    const int tid  = threadIdx.x;
    const int cta  = blockIdx.x;
    const int rank = cta & 7;            // k-slice / x-col-slice owner
    const int grp  = cta >> 3;
    const int b0   = grp * 8;
    const int k0   = rank * 32;
    const int skip = skipp ? skipp[0] : 4;
    unsigned* ctr  = &g_bars[grp * 32];
    unsigned  barno = 0;

    float2* Wrz = (float2*)(smem + OFF_WRZ);
    float*  Wn  = smem + OFF_WN;
    float*  Wo  = smem + OFF_WO;
    float*  hid = smem + OFF_HID;
    float*  sP  = smem + OFF_SP;
    float*  red = smem + OFF_RED;
    unsigned long long* redu  = (unsigned long long*)(smem + OFF_RED);
    unsigned long long* redpu = (unsigned long long*)(smem + OFF_REDP);
    float*  m0s = smem + OFF_M0;
    float*  m1s = smem + OFF_M1;
    const unsigned smem_u32 = (unsigned)__cvta_generic_to_shared(smem);

    // ================= one-time staging =================
    for (int i = tid; i < KK * 32; i += NTHR) {
        int kk = i >> 5, kl2 = i & 31;
        int k  = k0 + kl2;
        float r, z, n;
        if (kk < H_) {
            r = W_hh[(size_t)k * H_ + kk];
            z = W_hh[(size_t)(k + H_) * H_ + kk];
            n = W_hh[(size_t)(k + 2 * H_) * H_ + kk];
        } else {
            int xx = kk - H_;
            r = W_ih[k * X_ + xx];
            z = W_ih[(k + H_) * X_ + xx];
            n = W_ih[(k + 2 * H_) * X_ + xx];
        }
        Wrz[i] = make_float2(r, z);
        Wn[i]  = n;
    }
    for (int i = tid; i < H_ * 8; i += NTHR) {       // projection slice: cols [8r, 8r+8)
        int kk = i >> 3, xl2 = i & 7;
        Wo[i] = W_out[(size_t)(rank * 8 + xl2) * H_ + kk];
    }
    for (int i = tid; i < T_; i += NTHR) {
        m0s[i] = (float)mask0[i];
        m1s[i] = (float)mask1[i];
    }

    // per-thread constants
    float br = 0.f, bz = 0.f, bnh = 0.f, bni = 0.f;      // finalize biases
    {
        int k = k0 + (tid & 31);
        br  = b_ih[k] + b_hh[k];
        bz  = b_ih[k + H_] + b_hh[k + H_];
        bnh = b_hh[k + 2 * H_];
        bni = b_ih[k + 2 * H_];
    }
    float bo = 0.f;                                      // projection bias (tid<32)
    if (tid < 32) bo = b_out[rank * 8 + (tid & 7)];

    const int kl = tid & 31;
    const int q  = tid >> 5;                             // warp id 0..7
    const float2* wrzh = Wrz + q * 32 * 32 + kl;
    const float*  wnh  = Wn  + q * 32 * 32 + kl;
    const float2* wrzx = Wrz + (256 + q * 8) * 32 + kl;
    const float*  wnx  = Wn  + (256 + q * 8) * 32 + kl;
    const unsigned hidh = smem_u32 + (OFF_HID + q * 32 * 8) * 4;
    const unsigned hidx = smem_u32 + (OFF_HID + (256 + q * 8) * 8) * 4;
    // projection partial role
    const int xl  = tid & 7;
    const int bl2 = (tid >> 3) & 3;

    __syncthreads();

    // prefetched skip operands (held across the barrier window)
    float g[8], sp[8];
    #pragma unroll
    for (int j = 0; j < 8; ++j) { g[j] = 0.f; sp[j] = 0.f; }
    bool have = true;    // t=0: both zero

    for (int t = 0; t < T_; ++t) {
        int gidx, pidx; bool gz, pz, late;
        tables(t, skip, gidx, gz, pidx, pz, late);
        const bool usesp = (!pz) && (!late);

        // ---- fix-up sub-phase: previous step was "late" -> compute out(t-1) now ----
        if (t > 0) {
            int g2, p2; bool z2, q2, l2;
            tables(t - 1, skip, g2, z2, p2, q2, l2);
            if (l2) {
                // s = h(t-2) + h(p2), both in g_buf (or h_enc) after last barrier
                const float* a = (t >= 2) ? (g_buf + (size_t)(t - 2) * B_ * H_) : h_enc;
                const float* b = g_buf + (size_t)p2 * B_ * H_;
                int kk = tid;
                float v[8];
                #pragma unroll
                for (int j = 0; j < 8; ++j) {
                    float av = (t >= 2) ? __ldcg(a + (size_t)(b0 + j) * H_ + kk)
                                        : __ldg(a + (size_t)(b0 + j) * H_ + kk);
                    v[j] = av + __ldcg(b + (size_t)(b0 + j) * H_ + kk);
                }
                *(float4*)(sP + kk * 8)     = make_float4(v[0], v[1], v[2], v[3]);
                *(float4*)(sP + kk * 8 + 4) = make_float4(v[4], v[5], v[6], v[7]);
                __syncthreads();
                {
                    unsigned long long acc = 0;
                    #pragma unroll 8
                    for (int i = 0; i < 32; ++i) {
                        int kk2 = q * 32 + i;
                        unsigned long long s2 =
                            *(const unsigned long long*)(sP + kk2 * 8 + 2 * bl2);
                        float w = Wo[kk2 * 8 + xl];
                        fma2(acc, pk2(w, w), s2);
                    }
                    redpu[tid] = acc;
                }
                __syncthreads();
                if (tid < 32) {
                    unsigned long long a2 = 0;
                    #pragma unroll
                    for (int qq = 0; qq < 8; ++qq) a2 = add2(a2, redpu[qq * 32 + tid]);
                    float2 f = up2(a2);
                    f.x += bo; f.y += bo;
                    int xg = rank * 8 + (tid & 7);
                    int bb = (tid >> 3) & 3;
                    __stcg(out + ((size_t)(b0 + 2 * bb) * T_ + (t - 1)) * X_ + xg, f.x);
                    __stcg(out + ((size_t)(b0 + 2 * bb + 1) * T_ + (t - 1)) * X_ + xg, f.y);
                }
                // mini group barrier so everyone can read out(t-1)
                __syncthreads();
                if (tid == 0) bar_arrive(ctr);
                ++barno;
                if (tid == 0) { unsigned tgt = barno * GSIZE; while (bar_ld(ctr) < tgt) {} }
                __syncthreads();
            }
        }

        // ---- staging: gated hidden + projection input + x ----
        {
            float m0 = m0s[t], m1 = m1s[t];
            int kk = tid;
            if (!have) {   // deferred skip-operand loads (rare)
                #pragma unroll
                for (int j = 0; j < 8; ++j) {
                    g[j]  = gz ? 0.f
                               : __ldcg(g_buf + ((size_t)gidx * B_ + b0 + j) * H_ + kk);
                    sp[j] = usesp
                               ? __ldcg(g_buf + ((size_t)pidx * B_ + b0 + j) * H_ + kk)
                               : 0.f;
                }
            }
            const float* hsrc = t ? (g_buf + (size_t)(t - 1) * B_ * H_) : h_enc;
            float hv[8];
            #pragma unroll
            for (int j = 0; j < 8; ++j)
                hv[j] = t ? __ldcg(hsrc + (size_t)(b0 + j) * H_ + kk)
                          : __ldg(hsrc + (size_t)(b0 + j) * H_ + kk);
            float xv[8];
            if (tid < 64) {
                #pragma unroll
                for (int j = 0; j < 8; ++j)
                    xv[j] = t ? __ldcg(out + ((size_t)(b0 + j) * T_ + (t - 1)) * X_ + tid)
                              : 0.f;
            }
            *(float4*)(hid + kk * 8) =
                make_float4(hv[0] * m0 + g[0] * m1, hv[1] * m0 + g[1] * m1,
                            hv[2] * m0 + g[2] * m1, hv[3] * m0 + g[3] * m1);
            *(float4*)(hid + kk * 8 + 4) =
                make_float4(hv[4] * m0 + g[4] * m1, hv[5] * m0 + g[5] * m1,
                            hv[6] * m0 + g[6] * m1, hv[7] * m0 + g[7] * m1);
            *(float4*)(sP + kk * 8) =
                make_float4(hv[0] + sp[0], hv[1] + sp[1], hv[2] + sp[2], hv[3] + sp[3]);
            *(float4*)(sP + kk * 8 + 4) =
                make_float4(hv[4] + sp[4], hv[5] + sp[5], hv[6] + sp[6], hv[7] + sp[7]);
            if (tid < 64) {
                *(float4*)(hid + (256 + tid) * 8) =
                    make_float4(xv[0], xv[1], xv[2], xv[3]);
                *(float4*)(hid + (256 + tid) * 8 + 4) =
                    make_float4(xv[4], xv[5], xv[6], xv[7]);
            }
        }
        __syncthreads();

        // ---- gate GEMM: warp q owns h-seg [32q,32q+32) and x-seg [8q,8q+8) ----
        {
            unsigned long long ar[4], az[4], anh[4], ani[4];
            #pragma unroll
            for (int p = 0; p < 4; ++p) { ar[p] = 0; az[p] = 0; anh[p] = 0; ani[p] = 0; }
            #pragma unroll
            for (int i = 0; i < 32; ++i) {
                float2 w = wrzh[i * 32];
                float  wv = wnh[i * 32];
                unsigned long long wr2 = pk2(w.x, w.x);
                unsigned long long wz2 = pk2(w.y, w.y);
                unsigned long long wn2 = pk2(wv, wv);
                unsigned long long h01, h23, h45, h67;
                asm("ld.shared.v2.u64 {%0, %1}, [%2];"
                    : "=l"(h01), "=l"(h23) : "r"(hidh + i * 32));
                asm("ld.shared.v2.u64 {%0, %1}, [%2];"
                    : "=l"(h45), "=l"(h67) : "r"(hidh + i * 32 + 16));
                fma2(ar[0], wr2, h01); fma2(ar[1], wr2, h23);
                fma2(ar[2], wr2, h45); fma2(ar[3], wr2, h67);
                fma2(az[0], wz2, h01); fma2(az[1], wz2, h23);
                fma2(az[2], wz2, h45); fma2(az[3], wz2, h67);
                fma2(anh[0], wn2, h01); fma2(anh[1], wn2, h23);
                fma2(anh[2], wn2, h45); fma2(anh[3], wn2, h67);
            }
            #pragma unroll
            for (int j = 0; j < 8; ++j) {
                float2 w = wrzx[j * 32];
                float  wv = wnx[j * 32];
                unsigned long long wr2 = pk2(w.x, w.x);
                unsigned long long wz2 = pk2(w.y, w.y);
                unsigned long long wn2 = pk2(wv, wv);
                unsigned long long h01, h23, h45, h67;
                asm("ld.shared.v2.u64 {%0, %1}, [%2];"
                    : "=l"(h01), "=l"(h23) : "r"(hidx + j * 32));
                asm("ld.shared.v2.u64 {%0, %1}, [%2];"
                    : "=l"(h45), "=l"(h67) : "r"(hidx + j * 32 + 16));
                fma2(ar[0], wr2, h01); fma2(ar[1], wr2, h23);
                fma2(ar[2], wr2, h45); fma2(ar[3], wr2, h67);
                fma2(az[0], wz2, h01); fma2(az[1], wz2, h23);
                fma2(az[2], wz2, h45); fma2(az[3], wz2, h67);
                fma2(ani[0], wn2, h01); fma2(ani[1], wn2, h23);
                fma2(ani[2], wn2, h45); fma2(ani[3], wn2, h67);
            }
            unsigned long long* rp = redu + (q * 32 + kl) * 17;
            #pragma unroll
            for (int p = 0; p < 4; ++p) {
                rp[p * 4 + 0] = ar[p];
                rp[p * 4 + 1] = az[p];
                rp[p * 4 + 2] = anh[p];
                rp[p * 4 + 3] = ani[p];
            }
        }

        // ---- projection partials (overlaps; reads sP, stable since staging) ----
        if (!late) {
            unsigned long long acc = 0;
            #pragma unroll 8
            for (int i = 0; i < 32; ++i) {
                int kk2 = q * 32 + i;
                unsigned long long s2 =
                    *(const unsigned long long*)(sP + kk2 * 8 + 2 * bl2);
                float w = Wo[kk2 * 8 + xl];
                fma2(acc, pk2(w, w), s2);
            }
            redpu[tid] = acc;
        }
        __syncthreads();

        // ---- finalize h(t) + projection reduce ----
        {
            int bl = tid >> 5, klf = tid & 31;
            int p = bl >> 1, half = bl & 1;
            float sr = 0.f, sz = 0.f, snh = 0.f, sni = 0.f;
            #pragma unroll
            for (int qq = 0; qq < 8; ++qq) {
                const float* pr = red + (qq * 32 + klf) * 34 + p * 8 + half;
                sr  += pr[0];
                sz  += pr[2];
                snh += pr[4];
                sni += pr[6];
            }
            float r  = sig_fast(sr + br);
            float z  = sig_fast(sz + bz);
            float n  = tanh_fast(sni + bni + r * (snh + bnh));
            float hv = hid[(k0 + klf) * 8 + bl];
            float hn = (1.0f - z) * n + z * hv;
            __stcg(g_buf + ((size_t)t * B_ + (b0 + bl)) * H_ + (k0 + klf), hn);
        }
        if (!late && tid < 32) {
            unsigned long long a2 = 0;
            #pragma unroll
            for (int qq = 0; qq < 8; ++qq) a2 = add2(a2, redpu[qq * 32 + tid]);
            float2 f = up2(a2);
            f.x += bo; f.y += bo;
            int xg = rank * 8 + (tid & 7);
            int bb = (tid >> 3) & 3;
            __stcg(out + ((size_t)(b0 + 2 * bb) * T_ + t) * X_ + xg, f.x);
            __stcg(out + ((size_t)(b0 + 2 * bb + 1) * T_ + t) * X_ + xg, f.y);
        }

        // ---- group barrier with prefetch in the arrive->poll window ----
        __syncthreads();
        if (tid == 0) bar_arrive(ctr);
        ++barno;

        have = false;
        if (t + 1 < T_) {
            int ngidx, npidx; bool ngz, npz, nlate;
            tables(t + 1, skip, ngidx, ngz, npidx, npz, nlate);
            bool nuse = (!npz) && (!nlate);
            bool safe = (ngz || ngidx < t) && (!nuse || npidx < t);
            if (safe) {
                int kk = tid;
                #pragma unroll
                for (int j = 0; j < 8; ++j) {
                    g[j]  = ngz ? 0.f
                                : __ldcg(g_buf + ((size_t)ngidx * B_ + b0 + j) * H_ + kk);
                    sp[j] = nuse
                                ? __ldcg(g_buf + ((size_t)npidx * B_ + b0 + j) * H_ + kk)
                                : 0.f;
                }
                have = true;
            }
        }

        if (tid == 0) {
            unsigned tgt = barno * GSIZE;
            while (bar_ld(ctr) < tgt) {}
        }
        __syncthreads();
    }
}

extern "C" void kernel_launch(void* const* d_in, const int* in_sizes, int n_in,
                              void* d_out, int out_size) {
    // metadata order: input, h_enc, W_ih, W_hh, b_ih, b_hh, W_out, b_out, mask0, mask1, skip_size
    const float* h_enc = (const float*)d_in[1];
    const float* W_ih  = (const float*)d_in[2];
    const float* W_hh  = (const float*)d_in[3];
    const float* b_ih  = (const float*)d_in[4];
    const float* b_hh  = (const float*)d_in[5];
    const float* W_out = (const float*)d_in[6];
    const float* b_out = (const float*)d_in[7];
    const int*   mask0 = (const int*)d_in[8];
    const int*   mask1 = (const int*)d_in[9];
    const int*   skipp = (n_in > 10) ? (const int*)d_in[10] : (const int*)0;

    cudaFuncSetAttribute(decoder_kernel,
                         cudaFuncAttributeMaxDynamicSharedMemorySize, SMEM_BYTES);
    init_kernel<<<1, NGROUP * 32>>>();
    decoder_kernel<<<GRID_, NTHR, SMEM_BYTES>>>(
        h_enc, W_ih, W_hh, b_ih, b_hh, W_out, b_out, mask0, mask1, skipp,
        (float*)d_out);
}